// round 1
// baseline (speedup 1.0000x reference)
#include <cuda_runtime.h>

#define FG    2048
#define NTOT  262144
#define NB    (NTOT - FG)

// Scratch (no allocations allowed) — re-initialized by kernel A every launch.
__device__ float  g_sfg[FG];
__device__ int    g_cntLo[FG + 1];
__device__ int    g_dN[FG + 1];
__device__ double g_dX[FG + 1];
__device__ int    g_fcntLo[FG + 1];
__device__ int    g_fdN[FG + 1];
__device__ double g_fdX[FG + 1];

// first index i in [0,FG] with s[i] >= v  (s ascending, length FG)
__device__ __forceinline__ int lb2048(const float* s, float v) {
    int lo = 0, hi = FG;
    while (lo < hi) {
        int m = (lo + hi) >> 1;
        if (s[m] < v) lo = m + 1; else hi = m;
    }
    return lo;
}

// ---------------------------------------------------------------------------
// Kernel A: sort fg (bitonic, smem), zero accumulators, scatter fg->a_i terms
// ---------------------------------------------------------------------------
__global__ __launch_bounds__(1024) void kA_sort_init(const float* __restrict__ logits) {
    __shared__ float s[FG];
    int t = threadIdx.x;
    s[t]        = logits[t];
    s[t + 1024] = logits[t + 1024];
    __syncthreads();

    for (int k = 2; k <= FG; k <<= 1) {
        for (int j = k >> 1; j > 0; j >>= 1) {
            #pragma unroll
            for (int base = 0; base < FG; base += 1024) {
                int idx = base + t;
                int ixj = idx ^ j;
                if (ixj > idx) {
                    float a = s[idx], b = s[ixj];
                    bool up = ((idx & k) == 0);
                    if ((a > b) == up) { s[idx] = b; s[ixj] = a; }
                }
            }
            __syncthreads();
        }
    }

    g_sfg[t]        = s[t];
    g_sfg[t + 1024] = s[t + 1024];
    // zero all accumulators (FG+1 entries each)
    for (int i = t; i <= FG; i += 1024) {
        g_cntLo[i] = 0;  g_dN[i] = 0;  g_dX[i] = 0.0;
        g_fcntLo[i] = 0; g_fdN[i] = 0; g_fdX[i] = 0.0;
    }
    __syncthreads();

    // fg self-contributions (sources for a_i)
    #pragma unroll
    for (int base = 0; base < FG; base += 1024) {
        float x = s[base + t];
        int lo = lb2048(s, x - 1.0f);
        int hi = lb2048(s, x + 1.0f);
        atomicAdd(&g_fcntLo[lo], 1);
        if (lo < hi) {
            atomicAdd(&g_fdN[lo], 1);  atomicAdd(&g_fdN[hi], -1);
            atomicAdd(&g_fdX[lo], (double)x); atomicAdd(&g_fdX[hi], -(double)x);
        }
    }
}

// ---------------------------------------------------------------------------
// Kernel B: scatter bg contributions into difference arrays (smem -> global)
// ---------------------------------------------------------------------------
__global__ __launch_bounds__(256) void kB_scatter_bg(const float* __restrict__ logits,
                                                     const int* __restrict__ targets) {
    __shared__ float  s_fg[FG];
    __shared__ int    s_cntLo[FG + 1];
    __shared__ int    s_dN[FG + 1];
    __shared__ double s_dX[FG + 1];

    int t = threadIdx.x;
    for (int i = t; i < FG; i += 256) s_fg[i] = g_sfg[i];
    for (int i = t; i <= FG; i += 256) { s_cntLo[i] = 0; s_dN[i] = 0; s_dX[i] = 0.0; }
    __syncthreads();

    int stride = gridDim.x * blockDim.x;
    for (int j = blockIdx.x * blockDim.x + t; j < NB; j += stride) {
        if (targets[FG + j] != 0) continue;   // valid requires target==0; threshold part is vacuous
        float x = logits[FG + j];
        int lo = lb2048(s_fg, x - 1.0f);
        int hi = lb2048(s_fg, x + 1.0f);
        atomicAdd(&s_cntLo[lo], 1);           // queries i<lo get +1  (suffix-sum later)
        if (lo < hi) {                         // linear window [lo,hi)
            atomicAdd(&s_dN[lo], 1);  atomicAdd(&s_dN[hi], -1);
            atomicAdd(&s_dX[lo], (double)x); atomicAdd(&s_dX[hi], -(double)x);
        }
    }
    __syncthreads();

    for (int i = t; i <= FG; i += 256) {
        int    c = s_cntLo[i]; if (c) atomicAdd(&g_cntLo[i], c);
        int    n = s_dN[i];    if (n) atomicAdd(&g_dN[i], n);
        double x = s_dX[i];    if (x != 0.0) atomicAdd(&g_dX[i], x);
    }
}

// ---------------------------------------------------------------------------
// Kernel C: scans, cur = a/(a+b), running max, reduce -> metric
// ---------------------------------------------------------------------------
template <typename T>
__device__ __forceinline__ void scan2048_incl(T* a, T* tmp) {
    // inclusive prefix sum over a[0..2047]; blockDim.x == 1024
    int t = threadIdx.x;
    T v0 = a[2 * t], v1 = a[2 * t + 1];
    T ps = v0 + v1;
    tmp[t] = ps;
    __syncthreads();
    for (int d = 1; d < 1024; d <<= 1) {
        T add = (t >= d) ? tmp[t - d] : (T)0;
        __syncthreads();
        tmp[t] += add;
        __syncthreads();
    }
    T excl = tmp[t] - ps;
    a[2 * t]     = excl + v0;
    a[2 * t + 1] = excl + v0 + v1;
    __syncthreads();
}

__global__ __launch_bounds__(1024) void kC_finalize(float* __restrict__ out) {
    __shared__ float  s_fg[FG];
    __shared__ float  s_cur[FG];
    __shared__ double s_tmp[1024];

    int t = threadIdx.x;
    s_fg[t]        = g_sfg[t];
    s_fg[t + 1024] = g_sfg[t + 1024];
    __syncthreads();

    scan2048_incl<int>(g_cntLo,  (int*)s_tmp);
    scan2048_incl<int>(g_dN,     (int*)s_tmp);
    scan2048_incl<double>(g_dX,  s_tmp);
    scan2048_incl<int>(g_fcntLo, (int*)s_tmp);
    scan2048_incl<int>(g_fdN,    (int*)s_tmp);
    scan2048_incl<double>(g_fdX, s_tmp);

    int Tb = g_cntLo[FG - 1]  + g_cntLo[FG];   // total bg "full" counts
    int Tf = g_fcntLo[FG - 1] + g_fcntLo[FG];

    #pragma unroll
    for (int base = 0; base < FG; base += 1024) {
        int i = base + t;
        double fv = (double)s_fg[i];
        double b = (double)(Tb - g_cntLo[i])
                 + 0.5 * (g_dX[i] + (double)g_dN[i] * (1.0 - fv));
        double a = (double)(Tf - g_fcntLo[i])
                 + 0.5 * (g_fdX[i] + (double)g_fdN[i] * (1.0 - fv))
                 + 0.5;
        s_cur[i] = (float)(a / (a + b));
    }
    __syncthreads();

    // inclusive running-max scan over s_cur (ascending fv order)
    {
        float* ftmp = (float*)s_tmp;
        float v0 = s_cur[2 * t], v1 = s_cur[2 * t + 1];
        float pm = fmaxf(v0, v1);
        ftmp[t] = pm;
        __syncthreads();
        for (int d = 1; d < 1024; d <<= 1) {
            float add = (t >= d) ? ftmp[t - d] : -1e30f;
            __syncthreads();
            ftmp[t] = fmaxf(ftmp[t], add);
            __syncthreads();
        }
        float excl = (t > 0) ? ftmp[t - 1] : -1e30f;
        s_cur[2 * t]     = fmaxf(excl, v0);
        s_cur[2 * t + 1] = fmaxf(fmaxf(excl, v0), v1);
        __syncthreads();
    }

    // sum prec -> metric
    s_tmp[t] = (double)s_cur[2 * t] + (double)s_cur[2 * t + 1];
    __syncthreads();
    for (int d = 512; d > 0; d >>= 1) {
        if (t < d) s_tmp[t] += s_tmp[t + d];
        __syncthreads();
    }
    if (t == 0) out[0] = (float)(1.0 - s_tmp[0] / (double)FG);
}

// ---------------------------------------------------------------------------
extern "C" void kernel_launch(void* const* d_in, const int* in_sizes, int n_in,
                              void* d_out, int out_size) {
    const float* logits  = (const float*)d_in[0];
    const int*   targets = (const int*)d_in[1];
    float*       out     = (float*)d_out;
    (void)in_sizes; (void)n_in; (void)out_size;

    kA_sort_init<<<1, 1024>>>(logits);
    kB_scatter_bg<<<256, 256>>>(logits, targets);
    kC_finalize<<<1, 1024>>>(out);
}

// round 2
// speedup vs baseline: 1.9964x; 1.9964x over previous
#include <cuda_runtime.h>

#define FG    2048
#define NTOT  262144
#define G2    148          // scatter grid
#define K1B   64           // sort grid
#define EPB   32           // elements per k1 block
#define XSCALE 262144.0f   // 2^18 fixed-point scale
#define XBIAS  (1 << 21)   // per-add bias keeps low field positive
#define CNT_SHIFT 42
#define LOW_MASK  ((1ULL << CNT_SHIFT) - 1ULL)

// Scratch (no allocations allowed) — re-initialized by k1 every launch.
__device__ float               g_sfg[FG];
__device__ unsigned long long  g_A [FG + 1];   // bg: lo-side packed (count | biased fixed x)
__device__ unsigned long long  g_B [FG + 1];   // bg: hi-side packed
__device__ unsigned long long  g_AF[FG + 1];   // fg: lo-side
__device__ unsigned long long  g_BF[FG + 1];   // fg: hi-side
__device__ int                 g_done;

// branchless lower_bound over ascending s[0..2047]: first i with s[i] >= v
__device__ __forceinline__ int lb2048(const float* __restrict__ s, float v) {
    int lo = 0;
    #pragma unroll
    for (int step = 1024; step >= 1; step >>= 1)
        lo += (s[lo + step - 1] < v) ? step : 0;
    return lo;
}

__device__ __forceinline__ unsigned long long packx(float x) {
    int xq = __float2int_rn(x * XSCALE);
    return (1ULL << CNT_SHIFT) | (unsigned long long)(xq + XBIAS);
}

// ---------------------------------------------------------------------------
// k1: chip-wide rank sort of the 2048 fg logits + zero all accumulators.
// 64 blocks x 256 threads; each block owns 32 elements, 8 threads per element
// each count a 256-wide j-chunk (float4 smem broadcasts).
// ---------------------------------------------------------------------------
__global__ __launch_bounds__(256) void k1_sort(const float* __restrict__ logits) {
    __shared__ float s[FG];
    __shared__ int   scnt[EPB];
    int t = threadIdx.x;
    for (int i = t; i < FG; i += 256) s[i] = logits[i];
    if (t < EPB) scnt[t] = 0;
    __syncthreads();

    int el = t & (EPB - 1);                // local element 0..31
    int e  = blockIdx.x * EPB + el;        // global element index
    float x = s[e];
    int chunk = t >> 5;                    // 0..7 (8 threads per element)
    const float4* s4 = (const float4*)s;
    int q0 = chunk * 64;                   // 64 float4 = 256 elements per chunk
    int cnt = 0;
    #pragma unroll 4
    for (int q = q0; q < q0 + 64; q++) {
        float4 v = s4[q];
        int j = q * 4;
        cnt += (v.x < x) || (v.x == x && (j + 0) < e);
        cnt += (v.y < x) || (v.y == x && (j + 1) < e);
        cnt += (v.z < x) || (v.z == x && (j + 2) < e);
        cnt += (v.w < x) || (v.w == x && (j + 3) < e);
    }
    atomicAdd(&scnt[el], cnt);

    // zero global accumulators (16384 threads cover 2049 slots easily)
    int gid = blockIdx.x * 256 + t;
    if (gid <= FG) { g_A[gid] = 0; g_B[gid] = 0; g_AF[gid] = 0; g_BF[gid] = 0; }
    if (gid == 0) g_done = 0;

    __syncthreads();
    if (t < EPB) g_sfg[scnt[t]] = s[blockIdx.x * EPB + t];
}

// ---------------------------------------------------------------------------
// warp-based inclusive scan over 2048 packed values, 2 per thread (1024 thr)
// ---------------------------------------------------------------------------
__device__ __forceinline__ void scan2048_ull(
    unsigned long long v0, unsigned long long v1,
    unsigned long long* ws, int lane, int wid,
    unsigned long long& i0, unsigned long long& i1, unsigned long long& total)
{
    __syncthreads();                       // protect ws reuse across calls
    unsigned long long sv = v0 + v1;
    #pragma unroll
    for (int d = 1; d < 32; d <<= 1) {
        unsigned long long n = __shfl_up_sync(0xffffffffu, sv, d);
        if (lane >= d) sv += n;
    }
    if (lane == 31) ws[wid] = sv;
    __syncthreads();
    if (wid == 0) {
        unsigned long long w = ws[lane];
        #pragma unroll
        for (int d = 1; d < 32; d <<= 1) {
            unsigned long long n = __shfl_up_sync(0xffffffffu, w, d);
            if (lane >= d) w += n;
        }
        ws[lane] = w;
    }
    __syncthreads();
    unsigned long long ex = (wid ? ws[wid - 1] : 0ULL) + sv - v0 - v1;
    i0 = ex + v0;
    i1 = i0 + v1;
    total = ws[31];
}

__device__ __forceinline__ double unpack_val(unsigned long long v, long long& cnt) {
    cnt = (long long)(v >> CNT_SHIFT);
    long long lx = (long long)(v & LOW_MASK) - cnt * (long long)XBIAS;
    return (double)lx * (1.0 / (double)XSCALE);
}

// ---------------------------------------------------------------------------
// k2: scatter (bg -> smem histograms, fg -> global), flush, and the LAST
// finished block runs the entire finalize (scans + max-scan + reduce).
// ---------------------------------------------------------------------------
__global__ __launch_bounds__(1024) void k2_scatter_finalize(
    const float* __restrict__ logits, const int* __restrict__ targets,
    float* __restrict__ out)
{
    __shared__ float s_fg[FG];
    __shared__ unsigned long long sA[FG + 1], sB[FG + 1];
    __shared__ unsigned long long ws[32];
    __shared__ float  wsf[32];
    __shared__ double wsd[32];
    __shared__ int s_last;

    int t = threadIdx.x;
    s_fg[t]        = g_sfg[t];
    s_fg[t + 1024] = g_sfg[t + 1024];
    for (int i = t; i <= FG; i += 1024) { sA[i] = 0; sB[i] = 0; }
    __syncthreads();

    int stride = gridDim.x * 1024;
    for (int j = blockIdx.x * 1024 + t; j < NTOT; j += stride) {
        bool isfg = j < FG;
        if (!isfg && targets[j] != 0) continue;   // valid bg requires target==0
        float x = logits[j];
        int lo = lb2048(s_fg, x - 1.0f);
        int hi = lb2048(s_fg, x + 1.0f);
        unsigned long long p = packx(x);
        if (isfg) { atomicAdd(&g_AF[lo], p); atomicAdd(&g_BF[hi], p); }
        else      { atomicAdd(&sA[lo], p);   atomicAdd(&sB[hi], p);   }
    }
    __syncthreads();

    // flush block partials to global
    for (int i = t; i <= FG; i += 1024) {
        unsigned long long a = sA[i], b = sB[i];
        if (a) atomicAdd(&g_A[i], a);
        if (b) atomicAdd(&g_B[i], b);
    }
    __threadfence();
    if (t == 0) s_last = (atomicAdd(&g_done, 1) == (int)gridDim.x - 1);
    __syncthreads();
    if (!s_last) return;
    __threadfence();

    // ---------------- finalize (one block, 1024 threads) ----------------
    int lane = t & 31, wid = t >> 5;

    // bg scans
    unsigned long long A0 = __ldcg(&g_A[2 * t]), A1 = __ldcg(&g_A[2 * t + 1]);
    unsigned long long B0 = __ldcg(&g_B[2 * t]), B1 = __ldcg(&g_B[2 * t + 1]);
    unsigned long long IA0, IA1, TA, IB0, IB1, TBx;
    scan2048_ull(A0, A1, ws, lane, wid, IA0, IA1, TA);
    scan2048_ull(B0, B1, ws, lane, wid, IB0, IB1, TBx);
    long long TbCnt = (long long)((TA + __ldcg(&g_A[FG])) >> CNT_SHIFT);

    long long cA0, cA1, cB0, cB1;
    double xA0 = unpack_val(IA0, cA0), xA1 = unpack_val(IA1, cA1);
    double xB0 = unpack_val(IB0, cB0), xB1 = unpack_val(IB1, cB1);
    float fv0 = s_fg[2 * t], fv1 = s_fg[2 * t + 1];
    double b0 = (double)(TbCnt - cA0)
              + 0.5 * ((xA0 - xB0) + (double)(cA0 - cB0) * (1.0 - (double)fv0));
    double b1 = (double)(TbCnt - cA1)
              + 0.5 * ((xA1 - xB1) + (double)(cA1 - cB1) * (1.0 - (double)fv1));

    // fg scans
    unsigned long long F0 = __ldcg(&g_AF[2 * t]), F1 = __ldcg(&g_AF[2 * t + 1]);
    unsigned long long H0 = __ldcg(&g_BF[2 * t]), H1 = __ldcg(&g_BF[2 * t + 1]);
    unsigned long long IF0, IF1, TF, IH0, IH1, THx;
    scan2048_ull(F0, F1, ws, lane, wid, IF0, IF1, TF);
    scan2048_ull(H0, H1, ws, lane, wid, IH0, IH1, THx);
    long long TfCnt = (long long)((TF + __ldcg(&g_AF[FG])) >> CNT_SHIFT);

    long long cF0, cF1, cH0, cH1;
    double xF0 = unpack_val(IF0, cF0), xF1 = unpack_val(IF1, cF1);
    double xH0 = unpack_val(IH0, cH0), xH1 = unpack_val(IH1, cH1);
    double a0 = (double)(TfCnt - cF0)
              + 0.5 * ((xF0 - xH0) + (double)(cF0 - cH0) * (1.0 - (double)fv0)) + 0.5;
    double a1 = (double)(TfCnt - cF1)
              + 0.5 * ((xF1 - xH1) + (double)(cF1 - cH1) * (1.0 - (double)fv1)) + 0.5;

    float c0 = (float)(a0 / (a0 + b0));
    float c1 = (float)(a1 / (a1 + b1));

    // inclusive running-max over sorted order (prec), via warp max-scan
    float m = fmaxf(c0, c1);
    float mi = m;
    #pragma unroll
    for (int d = 1; d < 32; d <<= 1) {
        float n = __shfl_up_sync(0xffffffffu, mi, d);
        if (lane >= d) mi = fmaxf(mi, n);
    }
    if (lane == 31) wsf[wid] = mi;
    __syncthreads();
    if (wid == 0) {
        float w = wsf[lane];
        #pragma unroll
        for (int d = 1; d < 32; d <<= 1) {
            float n = __shfl_up_sync(0xffffffffu, w, d);
            if (lane >= d) w = fmaxf(w, n);
        }
        wsf[lane] = w;
    }
    __syncthreads();
    float wex  = wid ? wsf[wid - 1] : -1e30f;
    float prev = __shfl_up_sync(0xffffffffu, mi, 1);
    float ex   = (lane == 0) ? wex : fmaxf(wex, prev);
    float p0 = fmaxf(ex, c0);
    float p1 = fmaxf(p0, c1);

    // sum(prec) -> metric
    double sd = (double)p0 + (double)p1;
    #pragma unroll
    for (int d = 16; d >= 1; d >>= 1)
        sd += __shfl_down_sync(0xffffffffu, sd, d);
    if (lane == 0) wsd[wid] = sd;
    __syncthreads();
    if (t == 0) {
        double tot = 0.0;
        #pragma unroll
        for (int i = 0; i < 32; i++) tot += wsd[i];
        out[0] = (float)(1.0 - tot / (double)FG);
    }
}

// ---------------------------------------------------------------------------
extern "C" void kernel_launch(void* const* d_in, const int* in_sizes, int n_in,
                              void* d_out, int out_size) {
    const float* logits  = (const float*)d_in[0];
    const int*   targets = (const int*)d_in[1];
    float*       out     = (float*)d_out;
    (void)in_sizes; (void)n_in; (void)out_size;

    k1_sort<<<K1B, 256>>>(logits);
    k2_scatter_finalize<<<G2, 1024>>>(logits, targets, out);
}

// round 3
// speedup vs baseline: 2.1831x; 1.0935x over previous
#include <cuda_runtime.h>

#define FG    2048
#define NTOT  262144
#define G2    296         // scatter grid: 2 blocks/SM
#define K1B   64          // sort grid
#define EPB   32          // elements per k1 block
#define XSCALE 1048576.0f // 2^20 fixed-point scale
#define XBIAS  (1 << 23)  // per-add bias keeps low field positive
#define CNT_SHIFT 44
#define LOW_MASK  ((1ULL << CNT_SHIFT) - 1ULL)

#define NLUT  1024        // buckets over x in [-8, 8), width 1/64

// Scratch (no allocations allowed) — re-initialized by k1 every launch.
__device__ float               g_sfg[FG];
__device__ unsigned long long  g_A [FG + 1];   // bg: lo-side packed (count | biased fixed x)
__device__ unsigned long long  g_B [FG + 1];   // bg: hi-side packed
__device__ unsigned long long  g_AF[FG + 1];   // fg: lo-side
__device__ unsigned long long  g_BF[FG + 1];   // fg: hi-side
__device__ int                 g_done;

__device__ __forceinline__ unsigned long long packx(float x) {
    int xq = __float2int_rn(x * XSCALE);
    return (1ULL << CNT_SHIFT) | (unsigned long long)(xq + XBIAS);
}

__device__ __forceinline__ int bucket_of(float v) {
    int q = (int)floorf((v + 8.0f) * 64.0f);
    return min(max(q, 0), NLUT - 1);
}

// lower_bound of v in ascending s[], restricted to [lo, hi]
__device__ __forceinline__ int lbR(const float* __restrict__ s, float v, int lo, int hi) {
    while (lo < hi) {
        int m = (lo + hi) >> 1;
        if (s[m] < v) lo = m + 1; else hi = m;
    }
    return lo;
}

// ---------------------------------------------------------------------------
// k1: chip-wide rank sort of the 2048 fg logits + zero all accumulators.
// ---------------------------------------------------------------------------
__global__ __launch_bounds__(256) void k1_sort(const float* __restrict__ logits) {
    __shared__ float s[FG];
    __shared__ int   scnt[EPB];
    int t = threadIdx.x;
    for (int i = t; i < FG; i += 256) s[i] = logits[i];
    if (t < EPB) scnt[t] = 0;
    __syncthreads();

    int el = t & (EPB - 1);
    int e  = blockIdx.x * EPB + el;
    float x = s[e];
    int chunk = t >> 5;                    // 8 threads per element
    const float4* s4 = (const float4*)s;
    int q0 = chunk * 64;
    int cnt = 0;
    #pragma unroll 4
    for (int q = q0; q < q0 + 64; q++) {
        float4 v = s4[q];
        int j = q * 4;
        cnt += (v.x < x) || (v.x == x && (j + 0) < e);
        cnt += (v.y < x) || (v.y == x && (j + 1) < e);
        cnt += (v.z < x) || (v.z == x && (j + 2) < e);
        cnt += (v.w < x) || (v.w == x && (j + 3) < e);
    }
    atomicAdd(&scnt[el], cnt);

    int gid = blockIdx.x * 256 + t;
    if (gid <= FG) { g_A[gid] = 0; g_B[gid] = 0; g_AF[gid] = 0; g_BF[gid] = 0; }
    if (gid == 0) g_done = 0;

    __syncthreads();
    if (t < EPB) g_sfg[scnt[t]] = s[blockIdx.x * EPB + t];
}

// ---------------------------------------------------------------------------
// warp-based inclusive scan over 2048 packed values, 2 per thread (1024 thr)
// ---------------------------------------------------------------------------
__device__ __forceinline__ void scan2048_ull(
    unsigned long long v0, unsigned long long v1,
    unsigned long long* ws, int lane, int wid,
    unsigned long long& i0, unsigned long long& i1, unsigned long long& total)
{
    __syncthreads();
    unsigned long long sv = v0 + v1;
    #pragma unroll
    for (int d = 1; d < 32; d <<= 1) {
        unsigned long long n = __shfl_up_sync(0xffffffffu, sv, d);
        if (lane >= d) sv += n;
    }
    if (lane == 31) ws[wid] = sv;
    __syncthreads();
    if (wid == 0) {
        unsigned long long w = ws[lane];
        #pragma unroll
        for (int d = 1; d < 32; d <<= 1) {
            unsigned long long n = __shfl_up_sync(0xffffffffu, w, d);
            if (lane >= d) w += n;
        }
        ws[lane] = w;
    }
    __syncthreads();
    unsigned long long ex = (wid ? ws[wid - 1] : 0ULL) + sv - v0 - v1;
    i0 = ex + v0;
    i1 = i0 + v1;
    total = ws[31];
}

__device__ __forceinline__ double unpack_val(unsigned long long v, long long& cnt) {
    cnt = (long long)(v >> CNT_SHIFT);
    long long lx = (long long)(v & LOW_MASK) - cnt * (long long)XBIAS;
    return (double)lx * (1.0 / (double)XSCALE);
}

// ---------------------------------------------------------------------------
// k2: build LUT, scatter (bg -> smem histograms, fg -> global), flush,
// last-finished block runs the entire finalize.
// ---------------------------------------------------------------------------
__global__ __launch_bounds__(1024) void k2_scatter_finalize(
    const float* __restrict__ logits, const int* __restrict__ targets,
    float* __restrict__ out)
{
    __shared__ float s_fg[FG];
    __shared__ unsigned long long sA[FG + 1], sB[FG + 1];
    __shared__ int   s_lut[NLUT + 1];
    __shared__ unsigned long long ws[32];
    __shared__ float  wsf[32];
    __shared__ double wsd[32];
    __shared__ int s_last;

    int t = threadIdx.x;
    s_fg[t]        = g_sfg[t];
    s_fg[t + 1024] = g_sfg[t + 1024];
    for (int i = t; i <= FG; i += 1024) { sA[i] = 0; sB[i] = 0; }
    if (t <= NLUT) s_lut[t] = FG;
    __syncthreads();

    // Build LUT: s_lut[q] = first fg index with fg >= (q/64 - 8).
    // Each fg index i claims buckets q with boundary(q) in (fg[i-1], fg[i]].
    #pragma unroll
    for (int base = 0; base < FG; base += 1024) {
        int i = base + t;
        float cur  = s_fg[i];
        int bq = bucket_of(cur);
        int bp = (i == 0) ? -1 : bucket_of(s_fg[i - 1]);
        for (int q = bp + 1; q <= bq; q++) s_lut[q] = i;
    }
    __syncthreads();

    int stride = gridDim.x * 1024;
    for (int j = blockIdx.x * 1024 + t; j < NTOT; j += stride) {
        bool isfg = j < FG;
        if (!isfg && targets[j] != 0) continue;
        float x = logits[j];
        float vlo = x - 1.0f, vhi = x + 1.0f;
        int q1 = bucket_of(vlo), q2 = bucket_of(vhi);
        int lo = lbR(s_fg, vlo, s_lut[q1], s_lut[q1 + 1]);
        int hi = lbR(s_fg, vhi, s_lut[q2], s_lut[q2 + 1]);
        unsigned long long p = packx(x);
        if (isfg) { atomicAdd(&g_AF[lo], p); atomicAdd(&g_BF[hi], p); }
        else      { atomicAdd(&sA[lo], p);   atomicAdd(&sB[hi], p);   }
    }
    __syncthreads();

    // flush block partials to global (skip empty slots)
    for (int i = t; i <= FG; i += 1024) {
        unsigned long long a = sA[i], b = sB[i];
        if (a) atomicAdd(&g_A[i], a);
        if (b) atomicAdd(&g_B[i], b);
    }
    __threadfence();
    if (t == 0) s_last = (atomicAdd(&g_done, 1) == (int)gridDim.x - 1);
    __syncthreads();
    if (!s_last) return;
    __threadfence();

    // ---------------- finalize (one block, 1024 threads) ----------------
    int lane = t & 31, wid = t >> 5;

    unsigned long long A0 = __ldcg(&g_A[2 * t]), A1 = __ldcg(&g_A[2 * t + 1]);
    unsigned long long B0 = __ldcg(&g_B[2 * t]), B1 = __ldcg(&g_B[2 * t + 1]);
    unsigned long long IA0, IA1, TA, IB0, IB1, TBx;
    scan2048_ull(A0, A1, ws, lane, wid, IA0, IA1, TA);
    scan2048_ull(B0, B1, ws, lane, wid, IB0, IB1, TBx);
    long long TbCnt = (long long)((TA + __ldcg(&g_A[FG])) >> CNT_SHIFT);

    long long cA0, cA1, cB0, cB1;
    double xA0 = unpack_val(IA0, cA0), xA1 = unpack_val(IA1, cA1);
    double xB0 = unpack_val(IB0, cB0), xB1 = unpack_val(IB1, cB1);
    float fv0 = s_fg[2 * t], fv1 = s_fg[2 * t + 1];
    double b0 = (double)(TbCnt - cA0)
              + 0.5 * ((xA0 - xB0) + (double)(cA0 - cB0) * (1.0 - (double)fv0));
    double b1 = (double)(TbCnt - cA1)
              + 0.5 * ((xA1 - xB1) + (double)(cA1 - cB1) * (1.0 - (double)fv1));

    unsigned long long F0 = __ldcg(&g_AF[2 * t]), F1 = __ldcg(&g_AF[2 * t + 1]);
    unsigned long long H0 = __ldcg(&g_BF[2 * t]), H1 = __ldcg(&g_BF[2 * t + 1]);
    unsigned long long IF0, IF1, TF, IH0, IH1, THx;
    scan2048_ull(F0, F1, ws, lane, wid, IF0, IF1, TF);
    scan2048_ull(H0, H1, ws, lane, wid, IH0, IH1, THx);
    long long TfCnt = (long long)((TF + __ldcg(&g_AF[FG])) >> CNT_SHIFT);

    long long cF0, cF1, cH0, cH1;
    double xF0 = unpack_val(IF0, cF0), xF1 = unpack_val(IF1, cF1);
    double xH0 = unpack_val(IH0, cH0), xH1 = unpack_val(IH1, cH1);
    double a0 = (double)(TfCnt - cF0)
              + 0.5 * ((xF0 - xH0) + (double)(cF0 - cH0) * (1.0 - (double)fv0)) + 0.5;
    double a1 = (double)(TfCnt - cF1)
              + 0.5 * ((xF1 - xH1) + (double)(cF1 - cH1) * (1.0 - (double)fv1)) + 0.5;

    float c0 = (float)(a0 / (a0 + b0));
    float c1 = (float)(a1 / (a1 + b1));

    // inclusive running-max (prec) via warp max-scan
    float mi = fmaxf(c0, c1);
    #pragma unroll
    for (int d = 1; d < 32; d <<= 1) {
        float n = __shfl_up_sync(0xffffffffu, mi, d);
        if (lane >= d) mi = fmaxf(mi, n);
    }
    if (lane == 31) wsf[wid] = mi;
    __syncthreads();
    if (wid == 0) {
        float w = wsf[lane];
        #pragma unroll
        for (int d = 1; d < 32; d <<= 1) {
            float n = __shfl_up_sync(0xffffffffu, w, d);
            if (lane >= d) w = fmaxf(w, n);
        }
        wsf[lane] = w;
    }
    __syncthreads();
    float wex  = wid ? wsf[wid - 1] : -1e30f;
    float prev = __shfl_up_sync(0xffffffffu, mi, 1);
    float ex   = (lane == 0) ? wex : fmaxf(wex, prev);
    float p0 = fmaxf(ex, c0);
    float p1 = fmaxf(p0, c1);

    double sd = (double)p0 + (double)p1;
    #pragma unroll
    for (int d = 16; d >= 1; d >>= 1)
        sd += __shfl_down_sync(0xffffffffu, sd, d);
    if (lane == 0) wsd[wid] = sd;
    __syncthreads();
    if (t == 0) {
        double tot = 0.0;
        #pragma unroll
        for (int i = 0; i < 32; i++) tot += wsd[i];
        out[0] = (float)(1.0 - tot / (double)FG);
    }
}

// ---------------------------------------------------------------------------
extern "C" void kernel_launch(void* const* d_in, const int* in_sizes, int n_in,
                              void* d_out, int out_size) {
    const float* logits  = (const float*)d_in[0];
    const int*   targets = (const int*)d_in[1];
    float*       out     = (float*)d_out;
    (void)in_sizes; (void)n_in; (void)out_size;

    k1_sort<<<K1B, 256>>>(logits);
    k2_scatter_finalize<<<G2, 1024>>>(logits, targets, out);
}